// round 1
// baseline (speedup 1.0000x reference)
#include <cuda_runtime.h>
#include <math.h>

#define NROWS 8192
#define DIM   128
#define MFEAT 128
#define NB    64

#define PHI_EPS  1e-4f
#define NORM_EPS 1e-8f

// 128^-0.25
#define INV_D4   0.29730177875068026f
// 1/sqrt(128)
#define INV_SQM  0.08838834764831845f

// ---- device scratch (no allocs allowed) ----
__device__ float g_Qp[NROWS * MFEAT];
__device__ float g_UK[NROWS * MFEAT];
__device__ float g_hK[NROWS];
__device__ float g_Kp[NROWS * MFEAT];
__device__ float g_S[NB * MFEAT * DIM];
__device__ float g_Ksum[NB * MFEAT];
__device__ int   g_segmax[NB];     // float bits, init 0 (== clamp at 0.0f)
__device__ int   g_segstart[NB];
__device__ int   g_segend[NB];
__device__ int   g_is64;

// batch_seg may be int32 or int64 depending on jax x64 config.
__device__ __forceinline__ int get_seg(const int* __restrict__ segp, int i) {
    return g_is64 ? segp[2 * i] : segp[i];
}

// Detect int64 vs int32: batch_seg is sorted 0..63; in the upper half values
// are ~32+. If stored as int64 (LE), odd words there are 0.
__global__ void detect_kernel(const int* __restrict__ segp) {
    g_is64 = (segp[4097] == 0 && segp[4099] == 0 && segp[4101] == 0) ? 1 : 0;
}

__global__ void init_kernel() {
    int t = threadIdx.x;
    if (t < NB) {
        g_segmax[t]   = 0;       // float 0.0f bits
        g_segstart[t] = NROWS;
        g_segend[t]   = 0;
    }
}

__global__ void bounds_kernel(const int* __restrict__ segp) {
    int i = blockIdx.x * blockDim.x + threadIdx.x;
    if (i < NROWS) {
        int s = get_seg(segp, i);
        atomicMin(&g_segstart[s], i);
        atomicMax(&g_segend[s], i + 1);
    }
}

// ---------------------------------------------------------------------------
// U = (x * INV_D4) @ omega ; per-row h and max. 16 rows per block, 128 thr.
// ---------------------------------------------------------------------------
template <bool IS_Q>
__global__ void __launch_bounds__(128)
u_kernel(const float* __restrict__ X, const float* __restrict__ omega,
         const int* __restrict__ segp)
{
    __shared__ float xs[16][DIM];
    __shared__ float ws[32][MFEAT];
    __shared__ float red_h[16][4];
    __shared__ float red_m[16][4];
    __shared__ float hfin[16], mfin[16];

    int tid  = threadIdx.x;
    int lane = tid & 31;
    int wrp  = tid >> 5;
    int row0 = blockIdx.x * 16;

    float xv[16];
    float acc[16];
#pragma unroll
    for (int r = 0; r < 16; r++) {
        float v = X[(row0 + r) * DIM + tid] * INV_D4;
        xs[r][tid] = v;
        xv[r] = v;
        acc[r] = 0.0f;
    }

    for (int kc = 0; kc < 4; kc++) {
        __syncthreads();
#pragma unroll
        for (int kk = 0; kk < 32; kk++)
            ws[kk][tid] = omega[(kc * 32 + kk) * MFEAT + tid];
        __syncthreads();
#pragma unroll
        for (int kk = 0; kk < 32; kk++) {
            float w = ws[kk][tid];
#pragma unroll
            for (int r = 0; r < 16; r++)
                acc[r] = fmaf(xs[r][kc * 32 + kk], w, acc[r]);
        }
    }

    // per-row reductions: sum(x'^2) and max over m of U
#pragma unroll
    for (int r = 0; r < 16; r++) {
        float hs = xv[r] * xv[r];
        float mx = acc[r];
#pragma unroll
        for (int o = 16; o > 0; o >>= 1) {
            hs += __shfl_xor_sync(0xffffffffu, hs, o);
            mx = fmaxf(mx, __shfl_xor_sync(0xffffffffu, mx, o));
        }
        if (lane == 0) { red_h[r][wrp] = hs; red_m[r][wrp] = mx; }
    }
    __syncthreads();
    if (tid < 16) {
        float hs = red_h[tid][0] + red_h[tid][1] + red_h[tid][2] + red_h[tid][3];
        float mx = fmaxf(fmaxf(red_m[tid][0], red_m[tid][1]),
                         fmaxf(red_m[tid][2], red_m[tid][3]));
        // note: x' = x/d^0.25, so sum(x'^2) = sum(x^2)/sqrt(d); h = 0.5 * that
        hfin[tid] = 0.5f * hs;
        mfin[tid] = mx;
        if (!IS_Q) {
            int row = row0 + tid;
            g_hK[row] = 0.5f * hs;
            int s = get_seg(segp, row);
            atomicMax(&g_segmax[s], __float_as_int(mx));
        }
    }
    __syncthreads();

#pragma unroll
    for (int r = 0; r < 16; r++) {
        int idx = (row0 + r) * MFEAT + tid;
        if (IS_Q) {
            float qp = (expf(acc[r] - hfin[r] - mfin[r]) + PHI_EPS) * INV_SQM;
            g_Qp[idx] = qp;
        } else {
            g_UK[idx] = acc[r];
        }
    }
}

// Kp = (exp(U_K - h - segmax) + eps)/sqrt(m)
__global__ void __launch_bounds__(256)
kp_kernel(const int* __restrict__ segp)
{
    int idx = blockIdx.x * 256 + threadIdx.x;
    int i = idx >> 7;
    int s = get_seg(segp, i);
    float smax = __int_as_float(g_segmax[s]);
    g_Kp[idx] = (expf(g_UK[idx] - g_hK[i] - smax) + PHI_EPS) * INV_SQM;
}

// Ksum[b][m] = sum over segment rows of Kp[row][m]
__global__ void __launch_bounds__(128)
ksum_kernel()
{
    int b = blockIdx.x;
    int tid = threadIdx.x;
    int rs = g_segstart[b], re = g_segend[b];
    float s = 0.0f;
    for (int row = rs; row < re; row++)
        s += g_Kp[row * MFEAT + tid];
    g_Ksum[b * MFEAT + tid] = s;
}

// S[b][m][d] = sum over segment rows of Kp[row][m] * V[row][d]
// grid: (4 m-tiles of 32, NB segments), 128 threads (d = tid)
__global__ void __launch_bounds__(128)
s_kernel(const float* __restrict__ V)
{
    int mt = blockIdx.x;      // 0..3
    int b  = blockIdx.y;      // 0..63
    int tid = threadIdx.x;
    int rs = g_segstart[b], re = g_segend[b];

    __shared__ float kps[32];
    float acc[32];
#pragma unroll
    for (int mm = 0; mm < 32; mm++) acc[mm] = 0.0f;

    for (int row = rs; row < re; row++) {
        if (tid < 32)
            kps[tid] = g_Kp[row * MFEAT + mt * 32 + tid];
        __syncthreads();
        float v = V[row * DIM + tid];
#pragma unroll
        for (int mm = 0; mm < 32; mm++)
            acc[mm] = fmaf(kps[mm], v, acc[mm]);
        __syncthreads();
    }
#pragma unroll
    for (int mm = 0; mm < 32; mm++)
        g_S[(b * MFEAT + mt * 32 + mm) * DIM + tid] = acc[mm];
}

// out[i][d] = (Qp[i] . S[seg][:, d]) / (Qp[i] . Ksum[seg] + eps)
__global__ void __launch_bounds__(128)
out_kernel(const int* __restrict__ segp, float* __restrict__ out)
{
    int i = blockIdx.x;
    int tid = threadIdx.x;
    int lane = tid & 31, wrp = tid >> 5;
    int s = get_seg(segp, i);

    __shared__ float qs[MFEAT];
    __shared__ float rpart[4];

    float q = g_Qp[i * MFEAT + tid];
    qs[tid] = q;
    float p = q * g_Ksum[s * MFEAT + tid];
#pragma unroll
    for (int o = 16; o > 0; o >>= 1)
        p += __shfl_xor_sync(0xffffffffu, p, o);
    if (lane == 0) rpart[wrp] = p;
    __syncthreads();

    float norm = rpart[0] + rpart[1] + rpart[2] + rpart[3] + NORM_EPS;

    const float* Srow = g_S + s * MFEAT * DIM;
    float acc = 0.0f;
#pragma unroll 8
    for (int m = 0; m < MFEAT; m++)
        acc = fmaf(qs[m], Srow[m * DIM + tid], acc);

    out[i * DIM + tid] = acc / norm;
}

extern "C" void kernel_launch(void* const* d_in, const int* in_sizes, int n_in,
                              void* d_out, int out_size)
{
    const float* Q     = (const float*)d_in[0];
    const float* K     = (const float*)d_in[1];
    const float* V     = (const float*)d_in[2];
    const float* omega = (const float*)d_in[3];
    const int*   seg   = (const int*)d_in[4];
    float* out = (float*)d_out;

    detect_kernel<<<1, 1>>>(seg);
    init_kernel<<<1, 64>>>();
    bounds_kernel<<<(NROWS + 255) / 256, 256>>>(seg);

    u_kernel<true><<<NROWS / 16, 128>>>(Q, omega, seg);
    u_kernel<false><<<NROWS / 16, 128>>>(K, omega, seg);
    kp_kernel<<<(NROWS * MFEAT) / 256, 256>>>(seg);

    ksum_kernel<<<NB, 128>>>();
    s_kernel<<<dim3(4, NB), 128>>>(V);

    out_kernel<<<NROWS, 128>>>(seg, out);
}